// round 2
// baseline (speedup 1.0000x reference)
#include <cuda_runtime.h>

#define NODES_MAX 100000
#define C 256
#define GRAPHS 64
#define OUTC 10

// ---- scratch (no allocation allowed) ----
__device__ float g_hs[(size_t)NODES_MAX * C];    // h * dinv[row]
__device__ float g_agg[(size_t)NODES_MAX * C];   // sum over in-edges of hs[src]
__device__ float g_deg[NODES_MAX];
__device__ float g_dinv[NODES_MAX];
__device__ float g_sums[GRAPHS * C];
__device__ float g_counts[GRAPHS];
__device__ int   g_is64;                         // index dtype flag

// index load helper: works for int32 or int64 device buffers
__device__ __forceinline__ int load_idx(const void* p, long long i, int is64) {
    if (is64) return (int)((const long long*)p)[i];
    return ((const int*)p)[i];
}

// ---------------------------------------------------------------------------
// Detect index dtype: int64 little-endian values < 2^32 have all-zero odd words.
__global__ void detect_kernel(const int* __restrict__ ei32) {
    if (threadIdx.x == 0 && blockIdx.x == 0) {
        int nz = 0;
        #pragma unroll
        for (int i = 1; i < 256; i += 2) nz |= (ei32[i] != 0);
        g_is64 = (nz == 0) ? 1 : 0;
    }
}

// ---------------------------------------------------------------------------
__global__ void init_kernel(int n_nodes) {
    int total = n_nodes * C;
    for (int i = blockIdx.x * blockDim.x + threadIdx.x; i < total;
         i += gridDim.x * blockDim.x) {
        g_agg[i] = 0.f;
        if (i < n_nodes) g_deg[i] = 1.f;          // self-loop
        if (i < GRAPHS * C) g_sums[i] = 0.f;
        if (i < GRAPHS) g_counts[i] = 0.f;
    }
}

__global__ void deg_kernel(const void* __restrict__ ei, int E) {
    int i = blockIdx.x * blockDim.x + threadIdx.x;
    if (i >= E) return;
    int is64 = g_is64;
    int d = load_idx(ei, (long long)E + i, is64);
    atomicAdd(&g_deg[d], 1.f);
}

__global__ void dinv_kernel(int n) {
    int i = blockIdx.x * blockDim.x + threadIdx.x;
    if (i < n) g_dinv[i] = rsqrtf(g_deg[i]);
}

// ---------------------------------------------------------------------------
// hs = (x @ W1) * dinv[row].   M x 256 @ 256 x 256, fp32, 64x64 tiles.
#define BM 64
#define BN 64
#define BK 16
__global__ void gemm_kernel(const float* __restrict__ x,
                            const float* __restrict__ W1, int M) {
    __shared__ float As[BK][BM];   // As[k][r]
    __shared__ float Bs[BK][BN];   // Bs[k][c]

    int tid = threadIdx.x;          // 256 threads
    int tx = tid & 15;
    int ty = tid >> 4;
    int row0 = blockIdx.x * BM;
    int col0 = blockIdx.y * BN;

    float acc[4][4] = {};

    for (int kk = 0; kk < C; kk += BK) {
        {
            int r  = tid >> 2;            // 0..63
            int k0 = (tid & 3) * 4;       // 0,4,8,12
            int row = row0 + r;
            float4 a = (row < M)
                ? *(const float4*)(x + (size_t)row * C + kk + k0)
                : make_float4(0.f, 0.f, 0.f, 0.f);
            As[k0 + 0][r] = a.x;
            As[k0 + 1][r] = a.y;
            As[k0 + 2][r] = a.z;
            As[k0 + 3][r] = a.w;
        }
        {
            int k  = tid >> 4;            // 0..15
            int c4 = tid & 15;            // 0..15
            float4 b = *(const float4*)(W1 + (size_t)(kk + k) * C + col0 + c4 * 4);
            *(float4*)&Bs[k][c4 * 4] = b;
        }
        __syncthreads();

        #pragma unroll
        for (int k = 0; k < BK; k++) {
            float4 a4 = *(const float4*)&As[k][ty * 4];
            float4 b4 = *(const float4*)&Bs[k][tx * 4];
            float av[4] = {a4.x, a4.y, a4.z, a4.w};
            float bv[4] = {b4.x, b4.y, b4.z, b4.w};
            #pragma unroll
            for (int i = 0; i < 4; i++)
                #pragma unroll
                for (int j = 0; j < 4; j++)
                    acc[i][j] += av[i] * bv[j];
        }
        __syncthreads();
    }

    #pragma unroll
    for (int i = 0; i < 4; i++) {
        int row = row0 + ty * 4 + i;
        if (row >= M) continue;
        float s = g_dinv[row];
        float4 o = make_float4(acc[i][0] * s, acc[i][1] * s,
                               acc[i][2] * s, acc[i][3] * s);
        *(float4*)(g_hs + (size_t)row * C + col0 + tx * 4) = o;
    }
}

// ---------------------------------------------------------------------------
// For each edge: agg[dst] += hs[src]   (64 threads per edge, one v4 RED each)
__global__ void scatter_kernel(const void* __restrict__ ei, int E) {
    int t = threadIdx.x;
    int e = blockIdx.x * 4 + (t >> 6);
    if (e >= E) return;
    int is64 = g_is64;
    int c4  = t & 63;
    int src = load_idx(ei, e, is64);
    int dst = load_idx(ei, (long long)E + e, is64);
    float4 v = *(const float4*)(g_hs + (size_t)src * C + c4 * 4);
    float* a = g_agg + (size_t)dst * C + c4 * 4;
    asm volatile("red.global.v4.f32.add [%0], {%1, %2, %3, %4};"
                 :: "l"(a), "f"(v.x), "f"(v.y), "f"(v.z), "f"(v.w)
                 : "memory");
}

// ---------------------------------------------------------------------------
// pre_relu = dinv[i]*(agg[i] + hs[i]) + b1; relu; segmented sum over sorted
// batch ids with register accumulation + rare atomic flushes.
__global__ void pool_kernel(const void* __restrict__ batch,
                            const float* __restrict__ b1, int n) {
    const int NODES_PER_BLOCK = 128;
    int c = threadIdx.x;                     // channel 0..255
    int start = blockIdx.x * NODES_PER_BLOCK;
    if (start >= n) return;
    int end = min(start + NODES_PER_BLOCK, n);
    int is64 = g_is64;

    float bias = b1[c];
    int gp = load_idx(batch, start, is64);
    float acc = 0.f, cnt = 0.f;
    for (int i = start; i < end; i++) {
        int g = load_idx(batch, i, is64);
        if (g != gp) {
            atomicAdd(&g_sums[gp * C + c], acc);
            if (c == 0) atomicAdd(&g_counts[gp], cnt);
            acc = 0.f; cnt = 0.f; gp = g;
        }
        float v = g_dinv[i] * (g_agg[(size_t)i * C + c] + g_hs[(size_t)i * C + c]) + bias;
        acc += fmaxf(v, 0.f);
        cnt += 1.f;
    }
    atomicAdd(&g_sums[gp * C + c], acc);
    if (c == 0) atomicAdd(&g_counts[gp], cnt);
}

// ---------------------------------------------------------------------------
// out[g][o] = (sums[g] / max(count,1)) . W2[:,o] + b2[o]
__global__ void final_kernel(const float* __restrict__ W2,
                             const float* __restrict__ b2,
                             float* __restrict__ out) {
    int t = threadIdx.x;
    if (t >= GRAPHS * OUTC) return;
    int g = t / OUTC, o = t % OUTC;
    float s = 0.f;
    #pragma unroll 8
    for (int k = 0; k < C; k++)
        s += g_sums[g * C + k] * W2[k * OUTC + o];
    out[t] = s / fmaxf(g_counts[g], 1.f) + b2[o];
}

// ---------------------------------------------------------------------------
extern "C" void kernel_launch(void* const* d_in, const int* in_sizes, int n_in,
                              void* d_out, int out_size) {
    const float* x     = (const float*)d_in[0];
    const void*  ei    = d_in[1];
    const void*  batch = d_in[2];
    const float* W1    = (const float*)d_in[3];
    const float* b1    = (const float*)d_in[4];
    const float* W2    = (const float*)d_in[5];
    const float* b2    = (const float*)d_in[6];
    float* out = (float*)d_out;

    int n = in_sizes[0] / C;    // 100000
    int E = in_sizes[1] / 2;    // 1600000

    detect_kernel<<<1, 32>>>((const int*)ei);
    init_kernel<<<2048, 256>>>(n);
    deg_kernel<<<(E + 255) / 256, 256>>>(ei, E);
    dinv_kernel<<<(n + 255) / 256, 256>>>(n);

    dim3 ggrid((n + BM - 1) / BM, C / BN);
    gemm_kernel<<<ggrid, 256>>>(x, W1, n);

    scatter_kernel<<<(E + 3) / 4, 256>>>(ei, E);
    pool_kernel<<<(n + 127) / 128, 256>>>(batch, b1, n);
    final_kernel<<<1, 640>>>(W2, b2, out);
}

// round 4
// speedup vs baseline: 1.1800x; 1.1800x over previous
#include <cuda_runtime.h>
#include <cuda_bf16.h>
#include <cstdint>

#define NODES    100000
#define NODES_PAD 100096          // 782 * 128
#define C        256
#define KSPL     768              // K = 3 * 256 (hi*hi + hi*lo + lo*hi)
#define GRAPHS   64
#define OUTC     10
#define EMAX     1600000

// ---------------- scratch (static device globals; no allocation) ----------
__device__ __align__(16) __nv_bfloat16 g_A[(size_t)NODES_PAD * KSPL]; // [row][k]
__device__ __align__(16) __nv_bfloat16 g_B[(size_t)C * KSPL];         // [n][k]
__device__ float g_hs[(size_t)NODES_PAD * C];      // (x*dinv) @ W1
__device__ float g_hrelu[(size_t)NODES * C];       // relu(dinv*agg + b1)
__device__ float g_dinv[NODES];
__device__ int   g_degi[NODES];
__device__ int   g_rowptr[NODES + 1];
__device__ int   g_cursor[NODES];
__device__ int   g_elist[EMAX];
__device__ float g_sums[GRAPHS * C];
__device__ float g_counts[GRAPHS];
__device__ int   g_is64;

// ---------------- helpers ------------------------------------------------
__device__ __forceinline__ int load_idx(const void* p, long long i, int is64) {
    if (is64) return (int)((const long long*)p)[i];
    return ((const int*)p)[i];
}

__device__ __forceinline__ void mma16816(float* c, const uint32_t* a,
                                         const uint32_t* b) {
    asm volatile(
        "mma.sync.aligned.m16n8k16.row.col.f32.bf16.bf16.f32 "
        "{%0,%1,%2,%3}, {%4,%5,%6,%7}, {%8,%9}, {%0,%1,%2,%3};"
        : "+f"(c[0]), "+f"(c[1]), "+f"(c[2]), "+f"(c[3])
        : "r"(a[0]), "r"(a[1]), "r"(a[2]), "r"(a[3]), "r"(b[0]), "r"(b[1]));
}

// ---------------------------------------------------------------------------
__global__ void detect_kernel(const int* __restrict__ ei32) {
    if (threadIdx.x == 0 && blockIdx.x == 0) {
        int nz = 0;
        #pragma unroll
        for (int i = 1; i < 256; i += 2) nz |= (ei32[i] != 0);
        g_is64 = (nz == 0) ? 1 : 0;
    }
}

__global__ void init_kernel(int n) {
    int i = blockIdx.x * blockDim.x + threadIdx.x;
    if (i < n) g_degi[i] = 0;
    if (i < GRAPHS * C) g_sums[i] = 0.f;
    if (i < GRAPHS) g_counts[i] = 0.f;
}

__global__ void degi_kernel(const void* __restrict__ ei, int E) {
    int i = blockIdx.x * blockDim.x + threadIdx.x;
    if (i >= E) return;
    int d = load_idx(ei, (long long)E + i, g_is64);
    atomicAdd(&g_degi[d], 1);
}

// single-block exclusive scan over degrees -> rowptr + cursor
__global__ void scan_kernel(int n) {
    __shared__ int wsum[32];
    int t = threadIdx.x;
    const int CH = (n + 1023) >> 10;
    int start = min(t * CH, n), end = min(start + CH, n);
    int s = 0;
    for (int i = start; i < end; i++) s += g_degi[i];
    int lane = t & 31, wid = t >> 5;
    int v = s;
    #pragma unroll
    for (int d = 1; d < 32; d <<= 1) {
        int u = __shfl_up_sync(0xFFFFFFFFu, v, d);
        if (lane >= d) v += u;
    }
    if (lane == 31) wsum[wid] = v;
    __syncthreads();
    if (wid == 0) {
        int w = wsum[lane];
        #pragma unroll
        for (int d = 1; d < 32; d <<= 1) {
            int u = __shfl_up_sync(0xFFFFFFFFu, w, d);
            if (lane >= d) w += u;
        }
        wsum[lane] = w;
    }
    __syncthreads();
    int excl = v - s + (wid ? wsum[wid - 1] : 0);
    int run = excl;
    for (int i = start; i < end; i++) {
        g_rowptr[i] = run;
        g_cursor[i] = run;
        run += g_degi[i];
    }
    if (end == n) g_rowptr[n] = run;
}

__global__ void dinv_kernel(int n) {
    int i = blockIdx.x * blockDim.x + threadIdx.x;
    if (i < n) g_dinv[i] = rsqrtf((float)g_degi[i] + 1.f);
}

__global__ void place_kernel(const void* __restrict__ ei, int E) {
    int e = blockIdx.x * blockDim.x + threadIdx.x;
    if (e >= E) return;
    int is64 = g_is64;
    int src = load_idx(ei, e, is64);
    int dst = load_idx(ei, (long long)E + e, is64);
    int pos = atomicAdd(&g_cursor[dst], 1);
    g_elist[pos] = src;
}

// ---------------------------------------------------------------------------
// A' = [bf16(x*dinv) | bf16(x*dinv) | bf16(residual)], rows padded with zeros
__global__ void convert_kernel(const float* __restrict__ x, int n) {
    long long idx = (long long)blockIdx.x * blockDim.x + threadIdx.x;
    if (idx >= (long long)NODES_PAD * 128) return;
    int row = (int)(idx >> 7);
    int p = (int)(idx & 127);
    int c = p * 2;
    float v0 = 0.f, v1 = 0.f;
    if (row < n) {
        float d = g_dinv[row];
        v0 = x[(size_t)row * C + c] * d;
        v1 = x[(size_t)row * C + c + 1] * d;
    }
    __nv_bfloat16 h0 = __float2bfloat16(v0);
    __nv_bfloat16 h1 = __float2bfloat16(v1);
    __nv_bfloat162 hi2; hi2.x = h0; hi2.y = h1;
    __nv_bfloat162 lo2;
    lo2.x = __float2bfloat16(v0 - __bfloat162float(h0));
    lo2.y = __float2bfloat16(v1 - __bfloat162float(h1));
    __nv_bfloat162* base = (__nv_bfloat162*)(g_A + (size_t)row * KSPL);
    base[p]       = hi2;
    base[128 + p] = hi2;
    base[256 + p] = lo2;
}

// B' rows n: [W_hi(k) | W_lo(k) | W_hi(k)], K-major [n][k]
__global__ void bbuild_kernel(const float* __restrict__ W1) {
    int idx = blockIdx.x * blockDim.x + threadIdx.x;
    if (idx >= C * C) return;
    int nn = idx >> 8, k = idx & 255;
    float w = W1[(size_t)k * C + nn];
    __nv_bfloat16 hi = __float2bfloat16(w);
    __nv_bfloat16 lo = __float2bfloat16(w - __bfloat162float(hi));
    g_B[(size_t)nn * KSPL + k]       = hi;
    g_B[(size_t)nn * KSPL + 256 + k] = lo;
    g_B[(size_t)nn * KSPL + 512 + k] = hi;
}

// ---------------------------------------------------------------------------
// bf16 mma.sync GEMM:  hs[128 x 256 tile] = A'[128 x 768] @ B'^T[768 x 256]
// block: 256 thr (8 warps, 2(M) x 4(N)); warp tile 64x64; K-chunk 64 in smem.
#define APAD 72                   // padded row length (bf16 elems)
__global__ void __launch_bounds__(256) gemm_mma_kernel() {
    extern __shared__ __nv_bfloat16 smem[];
    __nv_bfloat16* As = smem;                 // [128][72]
    __nv_bfloat16* Bs = smem + 128 * APAD;    // [256][72]

    int tid = threadIdx.x;
    int wid = tid >> 5, lane = tid & 31;
    int g = lane >> 2, tir = lane & 3;
    int wm = wid & 1, wn = wid >> 1;          // warp grid 2 x 4
    int m0 = blockIdx.x * 128;

    float c[4][8][4];
    #pragma unroll
    for (int mt = 0; mt < 4; mt++)
        #pragma unroll
        for (int nt = 0; nt < 8; nt++)
            #pragma unroll
            for (int q = 0; q < 4; q++) c[mt][nt][q] = 0.f;

    for (int kc = 0; kc < KSPL / 64; kc++) {
        // load A chunk: 128 x 64 bf16
        const __nv_bfloat16* Ab = g_A + (size_t)m0 * KSPL + kc * 64;
        #pragma unroll
        for (int i = 0; i < 4; i++) {
            int u = tid + i * 256;
            int r = u >> 3, o = u & 7;
            uint4 v = *(const uint4*)(Ab + (size_t)r * KSPL + o * 8);
            *(uint4*)(As + r * APAD + o * 8) = v;
        }
        // load B chunk: 256 x 64 bf16
        #pragma unroll
        for (int i = 0; i < 8; i++) {
            int u = tid + i * 256;
            int r = u >> 3, o = u & 7;
            uint4 v = *(const uint4*)(g_B + (size_t)r * KSPL + kc * 64 + o * 8);
            *(uint4*)(Bs + r * APAD + o * 8) = v;
        }
        __syncthreads();

        #pragma unroll
        for (int ks = 0; ks < 4; ks++) {
            int kof = ks * 16 + tir * 2;
            uint32_t a[4][4];
            #pragma unroll
            for (int mt = 0; mt < 4; mt++) {
                int base = (wm * 64 + mt * 16 + g) * APAD + kof;
                a[mt][0] = *(const uint32_t*)(As + base);
                a[mt][1] = *(const uint32_t*)(As + base + 8 * APAD);
                a[mt][2] = *(const uint32_t*)(As + base + 8);
                a[mt][3] = *(const uint32_t*)(As + base + 8 * APAD + 8);
            }
            uint32_t b[8][2];
            #pragma unroll
            for (int nt = 0; nt < 8; nt++) {
                int base = (wn * 64 + nt * 8 + g) * APAD + kof;
                b[nt][0] = *(const uint32_t*)(Bs + base);
                b[nt][1] = *(const uint32_t*)(Bs + base + 8);
            }
            #pragma unroll
            for (int mt = 0; mt < 4; mt++)
                #pragma unroll
                for (int nt = 0; nt < 8; nt++)
                    mma16816(c[mt][nt], a[mt], b[nt]);
        }
        __syncthreads();
    }

    // epilogue: direct float2 stores
    #pragma unroll
    for (int mt = 0; mt < 4; mt++) {
        int row = m0 + wm * 64 + mt * 16 + g;
        #pragma unroll
        for (int nt = 0; nt < 8; nt++) {
            int col = wn * 64 + nt * 8 + tir * 2;
            *(float2*)(g_hs + (size_t)row * C + col) =
                make_float2(c[mt][nt][0], c[mt][nt][1]);
            *(float2*)(g_hs + (size_t)(row + 8) * C + col) =
                make_float2(c[mt][nt][2], c[mt][nt][3]);
        }
    }
}

// ---------------------------------------------------------------------------
// CSR gather: one block per dst node; fuses self-loop, dinv, bias, relu.
__global__ void gather_kernel(const float* __restrict__ b1, int n) {
    int i = blockIdx.x;
    int c = threadIdx.x;
    int r0 = g_rowptr[i], r1 = g_rowptr[i + 1];
    float a0 = g_hs[(size_t)i * C + c];      // self-loop term
    float a1 = 0.f, a2 = 0.f, a3 = 0.f;
    int j = r0;
    for (; j + 4 <= r1; j += 4) {
        int s0 = g_elist[j], s1 = g_elist[j + 1];
        int s2 = g_elist[j + 2], s3 = g_elist[j + 3];
        a0 += g_hs[(size_t)s0 * C + c];
        a1 += g_hs[(size_t)s1 * C + c];
        a2 += g_hs[(size_t)s2 * C + c];
        a3 += g_hs[(size_t)s3 * C + c];
    }
    for (; j < r1; j++) a0 += g_hs[(size_t)g_elist[j] * C + c];
    float v = g_dinv[i] * ((a0 + a1) + (a2 + a3)) + b1[c];
    g_hrelu[(size_t)i * C + c] = fmaxf(v, 0.f);
}

// ---------------------------------------------------------------------------
// segmented sum of hrelu over sorted batch ids
__global__ void pool_kernel(const void* __restrict__ batch, int n) {
    const int NPB = 128;
    int c = threadIdx.x;
    int start = blockIdx.x * NPB;
    if (start >= n) return;
    int end = min(start + NPB, n);
    int is64 = g_is64;

    int gp = load_idx(batch, start, is64);
    float acc = 0.f, cnt = 0.f;
    for (int i = start; i < end; i++) {
        int g = load_idx(batch, i, is64);
        if (g != gp) {
            atomicAdd(&g_sums[gp * C + c], acc);
            if (c == 0) atomicAdd(&g_counts[gp], cnt);
            acc = 0.f; cnt = 0.f; gp = g;
        }
        acc += g_hrelu[(size_t)i * C + c];
        cnt += 1.f;
    }
    atomicAdd(&g_sums[gp * C + c], acc);
    if (c == 0) atomicAdd(&g_counts[gp], cnt);
}

__global__ void final_kernel(const float* __restrict__ W2,
                             const float* __restrict__ b2,
                             float* __restrict__ out) {
    int t = threadIdx.x;
    if (t >= GRAPHS * OUTC) return;
    int g = t / OUTC, o = t % OUTC;
    float s = 0.f;
    #pragma unroll 8
    for (int k = 0; k < C; k++)
        s += g_sums[g * C + k] * W2[k * OUTC + o];
    out[t] = s / fmaxf(g_counts[g], 1.f) + b2[o];
}

// ---------------------------------------------------------------------------
extern "C" void kernel_launch(void* const* d_in, const int* in_sizes, int n_in,
                              void* d_out, int out_size) {
    const float* x     = (const float*)d_in[0];
    const void*  ei    = d_in[1];
    const void*  batch = d_in[2];
    const float* W1    = (const float*)d_in[3];
    const float* b1    = (const float*)d_in[4];
    const float* W2    = (const float*)d_in[5];
    const float* b2    = (const float*)d_in[6];
    float* out = (float*)d_out;

    int n = in_sizes[0] / C;    // 100000
    int E = in_sizes[1] / 2;    // 1600000

    detect_kernel<<<1, 32>>>((const int*)ei);
    init_kernel<<<(n + 255) / 256, 256>>>(n);
    degi_kernel<<<(E + 255) / 256, 256>>>(ei, E);
    scan_kernel<<<1, 1024>>>(n);
    dinv_kernel<<<(n + 255) / 256, 256>>>(n);

    convert_kernel<<<(NODES_PAD * 128 + 255) / 256, 256>>>(x, n);
    bbuild_kernel<<<256, 256>>>(W1);

    static const int SMEM_BYTES = (128 + 256) * APAD * 2;   // 55296
    cudaFuncSetAttribute(gemm_mma_kernel,
                         cudaFuncAttributeMaxDynamicSharedMemorySize, SMEM_BYTES);
    gemm_mma_kernel<<<NODES_PAD / 128, 256, SMEM_BYTES>>>();

    place_kernel<<<(E + 255) / 256, 256>>>(ei, E);
    gather_kernel<<<n, 256>>>(b1, n);
    pool_kernel<<<(n + 127) / 128, 256>>>(batch, n);
    final_kernel<<<1, 640>>>(W2, b2, out);
}

// round 6
// speedup vs baseline: 1.6155x; 1.3691x over previous
#include <cuda_runtime.h>
#include <cuda_bf16.h>
#include <cstdint>

#define NODES    100000
#define NODES_PAD 100096          // 782 * 128
#define C        256
#define ASTRIDE  512              // g_A row: [hi(256) | lo(256)]
#define KSPL     768              // logical K = 3 * 256 (hi*hi + hi*lo + lo*hi)
#define GRAPHS   64
#define OUTC     10
#define EMAX     1600000
#define NB1024   ((NODES + 1023) / 1024)

// ---------------- scratch (static device globals; no allocation) ----------
__device__ __align__(16) __nv_bfloat16 g_A[(size_t)NODES_PAD * ASTRIDE];
__device__ __align__(16) __nv_bfloat16 g_B[(size_t)C * KSPL];   // [n][k] K=768
__device__ float g_hs[(size_t)NODES_PAD * C];      // (x*dinv) @ W1
__device__ float g_hrelu[(size_t)NODES * C];       // relu(dinv*agg + b1)
__device__ float g_dinv[NODES];
__device__ int   g_degi[NODES];
__device__ int   g_rowptr[NODES + 1];
__device__ int   g_cursor[NODES];
__device__ int   g_elist[EMAX];
__device__ int   g_bsum[NB1024 + 1];
__device__ float g_sums[GRAPHS * C];
__device__ float g_counts[GRAPHS];
__device__ int   g_is64;

// ---------------- helpers ------------------------------------------------
__device__ __forceinline__ int load_idx(const void* p, long long i, int is64) {
    if (is64) return (int)((const long long*)p)[i];
    return ((const int*)p)[i];
}

__device__ __forceinline__ void mma16816(float* c, const uint32_t* a,
                                         const uint32_t* b) {
    asm volatile(
        "mma.sync.aligned.m16n8k16.row.col.f32.bf16.bf16.f32 "
        "{%0,%1,%2,%3}, {%4,%5,%6,%7}, {%8,%9}, {%0,%1,%2,%3};"
        : "+f"(c[0]), "+f"(c[1]), "+f"(c[2]), "+f"(c[3])
        : "r"(a[0]), "r"(a[1]), "r"(a[2]), "r"(a[3]), "r"(b[0]), "r"(b[1]));
}

__device__ __forceinline__ uint32_t smem_u32(const void* p) {
    uint32_t a;
    asm("{ .reg .u64 t; cvta.to.shared.u64 t, %1; cvt.u32.u64 %0, t; }"
        : "=r"(a) : "l"(p));
    return a;
}
__device__ __forceinline__ void cp16(uint32_t dst, const void* src) {
    asm volatile("cp.async.ca.shared.global [%0], [%1], 16;"
                 :: "r"(dst), "l"(src) : "memory");
}
#define CP_COMMIT() asm volatile("cp.async.commit_group;" ::: "memory")
#define CP_WAIT(N)  asm volatile("cp.async.wait_group %0;" :: "n"(N) : "memory")

// ---------------------------------------------------------------------------
__global__ void detect_kernel(const int* __restrict__ ei32) {
    if (threadIdx.x == 0 && blockIdx.x == 0) {
        int nz = 0;
        #pragma unroll
        for (int i = 1; i < 256; i += 2) nz |= (ei32[i] != 0);
        g_is64 = (nz == 0) ? 1 : 0;
    }
}

__global__ void init_kernel(int n) {
    int i = blockIdx.x * blockDim.x + threadIdx.x;
    if (i < n) g_degi[i] = 0;
    if (i < GRAPHS * C) g_sums[i] = 0.f;
    if (i < GRAPHS) g_counts[i] = 0.f;
}

__global__ void degi_kernel(const void* __restrict__ ei, int E) {
    int i = blockIdx.x * blockDim.x + threadIdx.x;
    if (i >= E) return;
    int d = load_idx(ei, (long long)E + i, g_is64);
    atomicAdd(&g_degi[d], 1);
}

// ---------------- hierarchical scan ----------------------------------------
// phase 1: per-block (1024-wide) exclusive scan, block totals to g_bsum
__global__ void scan1_kernel(int n) {
    __shared__ int wsum[32];
    int t = threadIdx.x;
    int i = blockIdx.x * 1024 + t;
    int v = (i < n) ? g_degi[i] : 0;
    int lane = t & 31, w = t >> 5;
    int inc = v;
    #pragma unroll
    for (int d = 1; d < 32; d <<= 1) {
        int u = __shfl_up_sync(0xFFFFFFFFu, inc, d);
        if (lane >= d) inc += u;
    }
    if (lane == 31) wsum[w] = inc;
    __syncthreads();
    if (w == 0) {
        int x = wsum[lane];
        #pragma unroll
        for (int d = 1; d < 32; d <<= 1) {
            int u = __shfl_up_sync(0xFFFFFFFFu, x, d);
            if (lane >= d) x += u;
        }
        wsum[lane] = x;
    }
    __syncthreads();
    int excl = inc - v + (w ? wsum[w - 1] : 0);
    if (i < n) g_rowptr[i] = excl;
    if (t == 1023) g_bsum[blockIdx.x] = excl + v;
}

// phase 2: single block scans the block sums (exclusive)
__global__ void scan2_kernel(int nb) {
    __shared__ int wsum[32];
    int t = threadIdx.x;                     // 1024 threads
    int v = (t < nb) ? g_bsum[t] : 0;
    int lane = t & 31, w = t >> 5;
    int inc = v;
    #pragma unroll
    for (int d = 1; d < 32; d <<= 1) {
        int u = __shfl_up_sync(0xFFFFFFFFu, inc, d);
        if (lane >= d) inc += u;
    }
    if (lane == 31) wsum[w] = inc;
    __syncthreads();
    if (w == 0) {
        int x = wsum[lane];
        #pragma unroll
        for (int d = 1; d < 32; d <<= 1) {
            int u = __shfl_up_sync(0xFFFFFFFFu, x, d);
            if (lane >= d) x += u;
        }
        wsum[lane] = x;
    }
    __syncthreads();
    int excl = inc - v + (w ? wsum[w - 1] : 0);
    if (t < nb) g_bsum[t] = excl;
}

// phase 3: fixup + cursor + fused dinv
__global__ void scan3_kernel(int n) {
    int i = blockIdx.x * blockDim.x + threadIdx.x;
    if (i >= n) return;
    int d = g_degi[i];
    int r = g_rowptr[i] + g_bsum[i >> 10];
    g_rowptr[i] = r;
    g_cursor[i] = r;
    g_dinv[i] = rsqrtf((float)d + 1.f);
    if (i == n - 1) g_rowptr[n] = r + d;
}

__global__ void place_kernel(const void* __restrict__ ei, int E) {
    int e = blockIdx.x * blockDim.x + threadIdx.x;
    if (e >= E) return;
    int is64 = g_is64;
    int src = load_idx(ei, e, is64);
    int dst = load_idx(ei, (long long)E + e, is64);
    int pos = atomicAdd(&g_cursor[dst], 1);
    g_elist[pos] = src;
}

// ---------------------------------------------------------------------------
// A = [bf16(x*dinv) | bf16(residual)], rows padded with zeros
__global__ void convert_kernel(const float* __restrict__ x, int n) {
    long long idx = (long long)blockIdx.x * blockDim.x + threadIdx.x;
    if (idx >= (long long)NODES_PAD * 128) return;
    int row = (int)(idx >> 7);
    int p = (int)(idx & 127);
    int c = p * 2;
    float v0 = 0.f, v1 = 0.f;
    if (row < n) {
        float d = g_dinv[row];
        v0 = x[(size_t)row * C + c] * d;
        v1 = x[(size_t)row * C + c + 1] * d;
    }
    __nv_bfloat16 h0 = __float2bfloat16(v0);
    __nv_bfloat16 h1 = __float2bfloat16(v1);
    __nv_bfloat162 hi2; hi2.x = h0; hi2.y = h1;
    __nv_bfloat162 lo2;
    lo2.x = __float2bfloat16(v0 - __bfloat162float(h0));
    lo2.y = __float2bfloat16(v1 - __bfloat162float(h1));
    __nv_bfloat162* base = (__nv_bfloat162*)(g_A + (size_t)row * ASTRIDE);
    base[p]       = hi2;
    base[128 + p] = lo2;
}

// B rows n: [W_hi(k) | W_lo(k) | W_hi(k)], K-major [n][k], K=768
__global__ void bbuild_kernel(const float* __restrict__ W1) {
    int idx = blockIdx.x * blockDim.x + threadIdx.x;
    if (idx >= C * C) return;
    int nn = idx >> 8, k = idx & 255;
    float w = W1[(size_t)k * C + nn];
    __nv_bfloat16 hi = __float2bfloat16(w);
    __nv_bfloat16 lo = __float2bfloat16(w - __bfloat162float(hi));
    g_B[(size_t)nn * KSPL + k]       = hi;
    g_B[(size_t)nn * KSPL + 256 + k] = lo;
    g_B[(size_t)nn * KSPL + 512 + k] = hi;
}

// ---------------------------------------------------------------------------
// bf16 mma.sync GEMM with cp.async double buffering.
// hs[128 x 256 tile] = A'[128 x 768] @ B'^T ; A hi-chunks deduped in memory.
#define APAD 72
#define STG_ELEMS ((128 + 256) * APAD)

// async load of one K-chunk stage into smem buffer s
__device__ __forceinline__ void load_stage(uint32_t sbase, int tid, int m0,
                                           int kc, int s) {
    uint32_t As = sbase + (uint32_t)(s * STG_ELEMS) * 2;
    uint32_t Bs = As + 128 * APAD * 2;
    int aoff = (kc & 3) * 64 + ((kc >= 8) ? 256 : 0);   // hi chunks reused
    const __nv_bfloat16* Ab = g_A + (size_t)m0 * ASTRIDE + aoff;
    #pragma unroll
    for (int i = 0; i < 4; i++) {
        int u = tid + i * 256;
        int r = u >> 3, o = u & 7;
        cp16(As + (uint32_t)(r * APAD + o * 8) * 2,
             Ab + (size_t)r * ASTRIDE + o * 8);
    }
    const __nv_bfloat16* Bb = g_B + kc * 64;
    #pragma unroll
    for (int i = 0; i < 8; i++) {
        int u = tid + i * 256;
        int r = u >> 3, o = u & 7;
        cp16(Bs + (uint32_t)(r * APAD + o * 8) * 2,
             Bb + (size_t)r * KSPL + o * 8);
    }
    CP_COMMIT();
}

__global__ void __launch_bounds__(256) gemm_mma_kernel() {
    extern __shared__ __nv_bfloat16 smem[];

    int tid = threadIdx.x;
    int wid = tid >> 5, lane = tid & 31;
    int g = lane >> 2, tir = lane & 3;
    int wm = wid & 1, wn = wid >> 1;          // warp grid 2 x 4
    int m0 = blockIdx.x * 128;

    uint32_t sbase = smem_u32(smem);
    const int NKC = KSPL / 64;                // 12 chunks

    float c[4][8][4];
    #pragma unroll
    for (int mt = 0; mt < 4; mt++)
        #pragma unroll
        for (int nt = 0; nt < 8; nt++)
            #pragma unroll
            for (int q = 0; q < 4; q++) c[mt][nt][q] = 0.f;

    load_stage(sbase, tid, m0, 0, 0);

    for (int kc = 0; kc < NKC; kc++) {
        if (kc + 1 < NKC) {
            load_stage(sbase, tid, m0, kc + 1, (kc + 1) & 1);
            CP_WAIT(1);
        } else {
            CP_WAIT(0);
        }
        __syncthreads();

        const __nv_bfloat16* As = smem + (kc & 1) * STG_ELEMS;
        const __nv_bfloat16* Bs = As + 128 * APAD;

        #pragma unroll
        for (int ks = 0; ks < 4; ks++) {
            int kof = ks * 16 + tir * 2;
            uint32_t a[4][4];
            #pragma unroll
            for (int mt = 0; mt < 4; mt++) {
                int base = (wm * 64 + mt * 16 + g) * APAD + kof;
                a[mt][0] = *(const uint32_t*)(As + base);
                a[mt][1] = *(const uint32_t*)(As + base + 8 * APAD);
                a[mt][2] = *(const uint32_t*)(As + base + 8);
                a[mt][3] = *(const uint32_t*)(As + base + 8 * APAD + 8);
            }
            uint32_t b[8][2];
            #pragma unroll
            for (int nt = 0; nt < 8; nt++) {
                int base = (wn * 64 + nt * 8 + g) * APAD + kof;
                b[nt][0] = *(const uint32_t*)(Bs + base);
                b[nt][1] = *(const uint32_t*)(Bs + base + 8);
            }
            #pragma unroll
            for (int mt = 0; mt < 4; mt++)
                #pragma unroll
                for (int nt = 0; nt < 8; nt++)
                    mma16816(c[mt][nt], a[mt], b[nt]);
        }
        __syncthreads();
    }

    // epilogue: direct float2 stores
    #pragma unroll
    for (int mt = 0; mt < 4; mt++) {
        int row = m0 + wm * 64 + mt * 16 + g;
        #pragma unroll
        for (int nt = 0; nt < 8; nt++) {
            int col = wn * 64 + nt * 8 + tir * 2;
            *(float2*)(g_hs + (size_t)row * C + col) =
                make_float2(c[mt][nt][0], c[mt][nt][1]);
            *(float2*)(g_hs + (size_t)(row + 8) * C + col) =
                make_float2(c[mt][nt][2], c[mt][nt][3]);
        }
    }
}

// ---------------------------------------------------------------------------
// CSR gather: one block per dst node; fuses self-loop, dinv, bias, relu.
__global__ void gather_kernel(const float* __restrict__ b1, int n) {
    int i = blockIdx.x;
    int c = threadIdx.x;
    int r0 = g_rowptr[i], r1 = g_rowptr[i + 1];
    float a0 = g_hs[(size_t)i * C + c];      // self-loop term
    float a1 = 0.f, a2 = 0.f, a3 = 0.f;
    int j = r0;
    for (; j + 4 <= r1; j += 4) {
        int s0 = g_elist[j], s1 = g_elist[j + 1];
        int s2 = g_elist[j + 2], s3 = g_elist[j + 3];
        a0 += g_hs[(size_t)s0 * C + c];
        a1 += g_hs[(size_t)s1 * C + c];
        a2 += g_hs[(size_t)s2 * C + c];
        a3 += g_hs[(size_t)s3 * C + c];
    }
    for (; j < r1; j++) a0 += g_hs[(size_t)g_elist[j] * C + c];
    float v = g_dinv[i] * ((a0 + a1) + (a2 + a3)) + b1[c];
    g_hrelu[(size_t)i * C + c] = fmaxf(v, 0.f);
}

// ---------------------------------------------------------------------------
// segmented sum of hrelu over sorted batch ids
__global__ void pool_kernel(const void* __restrict__ batch, int n) {
    const int NPB = 128;
    int c = threadIdx.x;
    int start = blockIdx.x * NPB;
    if (start >= n) return;
    int end = min(start + NPB, n);
    int is64 = g_is64;

    int gp = load_idx(batch, start, is64);
    float acc = 0.f, cnt = 0.f;
    for (int i = start; i < end; i++) {
        int g = load_idx(batch, i, is64);
        if (g != gp) {
            atomicAdd(&g_sums[gp * C + c], acc);
            if (c == 0) atomicAdd(&g_counts[gp], cnt);
            acc = 0.f; cnt = 0.f; gp = g;
        }
        acc += g_hrelu[(size_t)i * C + c];
        cnt += 1.f;
    }
    atomicAdd(&g_sums[gp * C + c], acc);
    if (c == 0) atomicAdd(&g_counts[gp], cnt);
}

__global__ void final_kernel(const float* __restrict__ W2,
                             const float* __restrict__ b2,
                             float* __restrict__ out) {
    int t = threadIdx.x;
    if (t >= GRAPHS * OUTC) return;
    int g = t / OUTC, o = t % OUTC;
    float s = 0.f;
    #pragma unroll 8
    for (int k = 0; k < C; k++)
        s += g_sums[g * C + k] * W2[k * OUTC + o];
    out[t] = s / fmaxf(g_counts[g], 1.f) + b2[o];
}

// ---------------------------------------------------------------------------
extern "C" void kernel_launch(void* const* d_in, const int* in_sizes, int n_in,
                              void* d_out, int out_size) {
    const float* x     = (const float*)d_in[0];
    const void*  ei    = d_in[1];
    const void*  batch = d_in[2];
    const float* W1    = (const float*)d_in[3];
    const float* b1    = (const float*)d_in[4];
    const float* W2    = (const float*)d_in[5];
    const float* b2    = (const float*)d_in[6];
    float* out = (float*)d_out;

    int n = in_sizes[0] / C;    // 100000
    int E = in_sizes[1] / 2;    // 1600000
    int nb = (n + 1023) / 1024;

    detect_kernel<<<1, 32>>>((const int*)ei);
    init_kernel<<<(n + 255) / 256, 256>>>(n);
    degi_kernel<<<(E + 255) / 256, 256>>>(ei, E);
    scan1_kernel<<<nb, 1024>>>(n);
    scan2_kernel<<<1, 1024>>>(nb);
    scan3_kernel<<<(n + 255) / 256, 256>>>(n);

    convert_kernel<<<(NODES_PAD * 128 + 255) / 256, 256>>>(x, n);
    bbuild_kernel<<<256, 256>>>(W1);

    static const int SMEM_BYTES = 2 * STG_ELEMS * 2;   // 110592
    cudaFuncSetAttribute(gemm_mma_kernel,
                         cudaFuncAttributeMaxDynamicSharedMemorySize, SMEM_BYTES);
    gemm_mma_kernel<<<NODES_PAD / 128, 256, SMEM_BYTES>>>();

    place_kernel<<<(E + 255) / 256, 256>>>(ei, E);
    gather_kernel<<<n, 256>>>(b1, n);
    pool_kernel<<<(n + 127) / 128, 256>>>(batch, n);
    final_kernel<<<1, 640>>>(W2, b2, out);
}